// round 3
// baseline (speedup 1.0000x reference)
#include <cuda_runtime.h>
#include <cuda_fp16.h>
#include <cstdint>
#include <cstddef>

#define N_NODES 16384
#define IN_F    128
#define OUT_F   64
#define NV      72      // V cols: 64 feats + 1 ones-column (denominator) + 7 pad
#define BI      64      // rows per CTA
#define BJ      128     // j-tile width
#define PSS     136     // P tile row stride in halves (conflict-free for ldmatrix)
#define MAIN_THREADS 128

// Scratch (device globals: allocation-free rule)
__device__ __align__(16) float  g_Wh[N_NODES * OUT_F];   // 4 MB fp32
__device__ __align__(16) __half g_V [N_NODES * NV];      // 2.25 MB fp16 (Wh + ones col)
__device__ __align__(16) float  g_fi[N_NODES];
__device__ __align__(16) float  g_fj[N_NODES];

// ---------------------------------------------------------------------------
// Kernel A: Wh = x @ W  (fp32), also write fp16 V with ones column
// ---------------------------------------------------------------------------
__global__ __launch_bounds__(256) void wh_kernel(const float* __restrict__ x,
                                                 const float* __restrict__ w) {
    __shared__ float ws[IN_F * OUT_F];   // 32 KB
    int tid = threadIdx.x;
    for (int t = tid; t < IN_F * OUT_F; t += 256) ws[t] = w[t];
    __syncthreads();

    int rl  = tid >> 3;                  // 0..31 local row
    int c0  = (tid & 7) * 8;             // 8-wide column group
    int row = blockIdx.x * 32 + rl;

    float acc[8];
#pragma unroll
    for (int j = 0; j < 8; j++) acc[j] = 0.f;

    const float* xr = x + (size_t)row * IN_F;
#pragma unroll 4
    for (int k = 0; k < IN_F; k++) {
        float xv = __ldg(&xr[k]);
#pragma unroll
        for (int j = 0; j < 8; j++)
            acc[j] = fmaf(xv, ws[k * OUT_F + c0 + j], acc[j]);
    }
#pragma unroll
    for (int j = 0; j < 8; j++) {
        g_Wh[(size_t)row * OUT_F + c0 + j] = acc[j];
        g_V[(size_t)row * NV + c0 + j]     = __float2half(acc[j]);
    }
    if ((tid & 7) == 0) {
        g_V[(size_t)row * NV + 64] = __float2half(1.0f);   // ones column -> denom
#pragma unroll
        for (int t = 65; t < NV; t++) g_V[(size_t)row * NV + t] = __float2half(0.0f);
    }
}

// ---------------------------------------------------------------------------
// Kernel B: f_i = Wh @ a[:64], f_j = Wh @ a[64:]
// ---------------------------------------------------------------------------
__global__ __launch_bounds__(256) void f_kernel(const float* __restrict__ aw) {
    int r = blockIdx.x * blockDim.x + threadIdx.x;
    const float4* whr = (const float4*)(g_Wh + (size_t)r * OUT_F);
    float fi = 0.f, fj = 0.f;
#pragma unroll
    for (int q = 0; q < 16; q++) {
        float4 v = whr[q];
        fi += v.x * __ldg(&aw[q * 4 + 0]) + v.y * __ldg(&aw[q * 4 + 1])
            + v.z * __ldg(&aw[q * 4 + 2]) + v.w * __ldg(&aw[q * 4 + 3]);
        fj += v.x * __ldg(&aw[64 + q * 4 + 0]) + v.y * __ldg(&aw[64 + q * 4 + 1])
            + v.z * __ldg(&aw[64 + q * 4 + 2]) + v.w * __ldg(&aw[64 + q * 4 + 3]);
    }
    g_fi[r] = fi;
    g_fj[r] = fj;
}

// ---------------------------------------------------------------------------
// Main fused kernel: masked softmax(leaky(f_i + f_j^T)) @ Wh, then ELU.
// CTA = 64 rows (4 warps x m16), loop over 128-wide j tiles.
// P tile fp16 in smem, V tile fp16 in smem (with ones col), HMMA m16n8k16.
// ---------------------------------------------------------------------------
__global__ __launch_bounds__(MAIN_THREADS) void gat_main(const int* __restrict__ adj,
                                                         float* __restrict__ out) {
    __shared__ __align__(16) __half Ps[BI * PSS];   // 17408 B
    __shared__ __align__(16) __half Vs[BJ * NV];    // 18432 B
    __shared__ float fis[BI];

    int tid  = threadIdx.x;
    int lane = tid & 31;
    int warp = tid >> 5;
    int i0   = blockIdx.x * BI;

    if (tid < BI) fis[tid] = g_fi[i0 + tid];
    __syncthreads();

    float c[9][4];
#pragma unroll
    for (int ng = 0; ng < 9; ng++)
#pragma unroll
        for (int q = 0; q < 4; q++) c[ng][q] = 0.f;

    int m0 = warp * 16;
    uint32_t ps_u32 = (uint32_t)__cvta_generic_to_shared(Ps);
    uint32_t vs_u32 = (uint32_t)__cvta_generic_to_shared(Vs);
    // A-fragment base address (ldmatrix.x4 over 16x16 row-major tile)
    uint32_t a_base = ps_u32 + 2u * ((m0 + (lane & 15)) * PSS + (lane >> 4) * 8);

    for (int j0 = 0; j0 < N_NODES; j0 += BJ) {
        // ---- load V tile: 128 x 72 halves = 1152 uint4, 9 per thread ----
        {
            const uint4* vsrc = (const uint4*)(g_V + (size_t)j0 * NV);
            uint4* vdst = (uint4*)Vs;
#pragma unroll
            for (int t = 0; t < 9; t++)
                vdst[tid + t * MAIN_THREADS] = vsrc[tid + t * MAIN_THREADS];
        }

        // ---- compute P tile (64 x 128), MLP=16 adj loads per batch ----
        float fjv = __ldg(&g_fj[j0 + tid]);
        const int* adjp = adj + (size_t)i0 * N_NODES + j0 + tid;
#pragma unroll
        for (int s0 = 0; s0 < BI; s0 += 16) {
            int av[16];
#pragma unroll
            for (int u = 0; u < 16; u++)
                av[u] = __ldg(adjp + (size_t)(s0 + u) * N_NODES);
#pragma unroll
            for (int u = 0; u < 16; u++) {
                float e = fis[s0 + u] + fjv;
                e = e > 0.f ? e : 0.02f * e;                 // leaky_relu
                float p = av[u] > 0 ? __expf(e) : 0.f;       // mask -> exp or 0
                Ps[(s0 + u) * PSS + tid] = __float2half(p);
            }
        }
        __syncthreads();

        // ---- MMA: C[16 x 72] += P[16 x 128] @ V[128 x 72] per warp ----
#pragma unroll
        for (int kk = 0; kk < BJ / 16; kk++) {
            uint32_t a0, a1, a2, a3;
            uint32_t aaddr = a_base + kk * 32;               // 16 halves per k-step
            asm volatile("ldmatrix.sync.aligned.m8n8.x4.shared.b16 {%0,%1,%2,%3}, [%4];"
                         : "=r"(a0), "=r"(a1), "=r"(a2), "=r"(a3) : "r"(aaddr));
            uint32_t brow = vs_u32 + 2u * ((kk * 16 + (lane & 15)) * NV);
#pragma unroll
            for (int ng = 0; ng < 9; ng++) {
                uint32_t b0, b1;
                uint32_t baddr = brow + ng * 16;             // 8 halves per n-tile
                asm volatile("ldmatrix.sync.aligned.m8n8.x2.trans.shared.b16 {%0,%1}, [%2];"
                             : "=r"(b0), "=r"(b1) : "r"(baddr));
                asm volatile("mma.sync.aligned.m16n8k16.row.col.f32.f16.f16.f32 "
                             "{%0,%1,%2,%3}, {%4,%5,%6,%7}, {%8,%9}, {%0,%1,%2,%3};"
                             : "+f"(c[ng][0]), "+f"(c[ng][1]), "+f"(c[ng][2]), "+f"(c[ng][3])
                             : "r"(a0), "r"(a1), "r"(a2), "r"(a3), "r"(b0), "r"(b1));
            }
        }
        __syncthreads();
    }

    // ---- epilogue: denom from ones column (ng=8, col 64, lanes with lane%4==0) ----
    float d0 = __shfl_sync(0xffffffffu, c[8][0], lane & ~3);  // row = lane/4
    float d1 = __shfl_sync(0xffffffffu, c[8][2], lane & ~3);  // row = lane/4 + 8
    float inv0 = 1.0f / d0;
    float inv1 = 1.0f / d1;

    int r0  = i0 + m0 + (lane >> 2);
    int col = (lane & 3) * 2;
#pragma unroll
    for (int ng = 0; ng < 8; ng++) {
        float h0 = c[ng][0] * inv0;
        float h1 = c[ng][1] * inv0;
        float h2 = c[ng][2] * inv1;
        float h3 = c[ng][3] * inv1;
        h0 = h0 > 0.f ? h0 : expm1f(h0);                      // ELU
        h1 = h1 > 0.f ? h1 : expm1f(h1);
        h2 = h2 > 0.f ? h2 : expm1f(h2);
        h3 = h3 > 0.f ? h3 : expm1f(h3);
        *(float2*)&out[(size_t)r0 * OUT_F + ng * 8 + col]       = make_float2(h0, h1);
        *(float2*)&out[(size_t)(r0 + 8) * OUT_F + ng * 8 + col] = make_float2(h2, h3);
    }
}

// ---------------------------------------------------------------------------
extern "C" void kernel_launch(void* const* d_in, const int* in_sizes, int n_in,
                              void* d_out, int out_size) {
    const float* x   = (const float*)d_in[0];   // [16384, 128] f32
    const int*   adj = (const int*)d_in[1];     // [16384, 16384] i32
    const float* w   = (const float*)d_in[2];   // [128, 64] f32
    const float* aw  = (const float*)d_in[3];   // [128, 1] f32
    float* out = (float*)d_out;                 // [16384, 64] f32

    wh_kernel<<<N_NODES / 32, 256>>>(x, w);
    f_kernel<<<N_NODES / 256, 256>>>(aw);
    gat_main<<<N_NODES / BI, MAIN_THREADS>>>(adj, out);
}

// round 5
// speedup vs baseline: 2.3220x; 2.3220x over previous
#include <cuda_runtime.h>
#include <cuda_fp16.h>
#include <cstdint>
#include <cstddef>

#define N_NODES 16384
#define IN_F    128
#define OUT_F   64
#define NV      72      // V cols: 64 feats + ones col (denominator) + 7 pad
#define BI      64      // rows per CTA
#define BJ      128     // j-tile width
#define PSS     136     // P row stride (halves), conflict-free for ldmatrix
#define JSPLIT  4
#define JTILES  (N_NODES / JSPLIT / BJ)   // 32
#define IBLOCKS (N_NODES / BI)            // 256

#define PS_BYTES (BI * PSS * 2)           // 17408
#define VS_BYTES (BJ * NV * 2)            // 18432
#define SMEM_TOTAL (2 * PS_BYTES + 2 * VS_BYTES + BI * 16)  // 72704

// Scratch (device globals: allocation-free rule)
__device__ __align__(16) float  g_Wh[N_NODES * OUT_F];
__device__ __align__(16) __half g_V [N_NODES * NV];
__device__ __align__(16) float4 g_rowc[N_NODES];   // {-fi, e^fi, e^{.02fi}, 0}
__device__ __align__(16) float4 g_colc[N_NODES];   // { fj, e^fj, e^{.02fj}, 0}
__device__ __align__(16) float  g_part[(size_t)JSPLIT * IBLOCKS * BI * NV];

// ---------------------------------------------------------------------------
// Kernel A: Wh = x @ W (fp32) + fp16 V with ones column
// ---------------------------------------------------------------------------
__global__ __launch_bounds__(256) void wh_kernel(const float* __restrict__ x,
                                                 const float* __restrict__ w) {
    __shared__ float ws[IN_F * OUT_F];
    int tid = threadIdx.x;
    for (int t = tid; t < IN_F * OUT_F; t += 256) ws[t] = w[t];
    __syncthreads();

    int rl  = tid >> 3;
    int c0  = (tid & 7) * 8;
    int row = blockIdx.x * 32 + rl;

    float acc[8];
#pragma unroll
    for (int j = 0; j < 8; j++) acc[j] = 0.f;

    const float4* xr = (const float4*)(x + (size_t)row * IN_F);
#pragma unroll 8
    for (int q = 0; q < 32; q++) {
        float4 xv = __ldg(&xr[q]);
        int k = q * 4;
#pragma unroll
        for (int j = 0; j < 8; j++) acc[j] = fmaf(xv.x, ws[(k + 0) * OUT_F + c0 + j], acc[j]);
#pragma unroll
        for (int j = 0; j < 8; j++) acc[j] = fmaf(xv.y, ws[(k + 1) * OUT_F + c0 + j], acc[j]);
#pragma unroll
        for (int j = 0; j < 8; j++) acc[j] = fmaf(xv.z, ws[(k + 2) * OUT_F + c0 + j], acc[j]);
#pragma unroll
        for (int j = 0; j < 8; j++) acc[j] = fmaf(xv.w, ws[(k + 3) * OUT_F + c0 + j], acc[j]);
    }
#pragma unroll
    for (int j = 0; j < 8; j++) {
        g_Wh[(size_t)row * OUT_F + c0 + j] = acc[j];
        g_V[(size_t)row * NV + c0 + j]     = __float2half(acc[j]);
    }
    if ((tid & 7) == 0) {
        g_V[(size_t)row * NV + 64] = __float2half(1.0f);
#pragma unroll
        for (int t = 65; t < NV; t++) g_V[(size_t)row * NV + t] = __float2half(0.0f);
    }
}

// ---------------------------------------------------------------------------
// Kernel B: attention scalars + exp tables
// ---------------------------------------------------------------------------
__global__ __launch_bounds__(256) void f_kernel(const float* __restrict__ aw) {
    int r = blockIdx.x * blockDim.x + threadIdx.x;
    const float4* whr = (const float4*)(g_Wh + (size_t)r * OUT_F);
    float fi = 0.f, fj = 0.f;
#pragma unroll
    for (int q = 0; q < 16; q++) {
        float4 v = whr[q];
        fi += v.x * __ldg(&aw[q * 4 + 0]) + v.y * __ldg(&aw[q * 4 + 1])
            + v.z * __ldg(&aw[q * 4 + 2]) + v.w * __ldg(&aw[q * 4 + 3]);
        fj += v.x * __ldg(&aw[64 + q * 4 + 0]) + v.y * __ldg(&aw[64 + q * 4 + 1])
            + v.z * __ldg(&aw[64 + q * 4 + 2]) + v.w * __ldg(&aw[64 + q * 4 + 3]);
    }
    g_rowc[r] = make_float4(-fi, expf(fi), expf(0.02f * fi), 0.f);
    g_colc[r] = make_float4(fj,  expf(fj), expf(0.02f * fj), 0.f);
}

// ---------------------------------------------------------------------------
// Main fused kernel: per (i-block, j-split): partial P@V with ones column.
// Double-buffered Ps/Vs, ONE barrier per tile. No MUFU in hot loop.
// ---------------------------------------------------------------------------
__global__ __launch_bounds__(128, 3) void gat_main(const int* __restrict__ adj) {
    extern __shared__ __align__(16) char sm[];
    __half* Ps = (__half*)sm;
    __half* Vs = (__half*)(sm + 2 * PS_BYTES);
    float4* rowc = (float4*)(sm + 2 * PS_BYTES + 2 * VS_BYTES);

    int tid  = threadIdx.x;
    int lane = tid & 31;
    int warp = tid >> 5;
    int i0    = blockIdx.x * BI;
    int jbase = blockIdx.y * (N_NODES / JSPLIT);

    if (tid < BI) rowc[tid] = g_rowc[i0 + tid];
    __syncthreads();

    float c[9][4];
#pragma unroll
    for (int ng = 0; ng < 9; ng++)
#pragma unroll
        for (int q = 0; q < 4; q++) c[ng][q] = 0.f;

    // producer mapping: 2 cols x 32 rows per thread
    int rhalf = tid >> 6;          // 0/1 -> rows [0,32) / [32,64)
    int c0    = (tid & 63) * 2;    // column pair

    uint32_t ps_u = (uint32_t)__cvta_generic_to_shared(Ps);
    uint32_t vs_u = (uint32_t)__cvta_generic_to_shared(Vs);
    int m0 = warp * 16;
    uint32_t a_off = 2u * ((m0 + (lane & 15)) * PSS + (lane >> 4) * 8);

    for (int t = 0; t < JTILES; t++) {
        int j0  = jbase + t * BJ;
        int buf = t & 1;

        // ---- V tile into buf ----
        {
            const uint4* vsrc = (const uint4*)(g_V + (size_t)j0 * NV);
            uint4* vdst = (uint4*)(Vs + buf * (BJ * NV));
#pragma unroll
            for (int q = 0; q < 9; q++)
                vdst[tid + q * 128] = vsrc[tid + q * 128];
        }

        // ---- P tile into buf: select-multiply, no exp ----
        float4 C0 = __ldg(&g_colc[j0 + c0]);
        float4 C1 = __ldg(&g_colc[j0 + c0 + 1]);
        const int* adjp = adj + (size_t)(i0 + rhalf * 32) * N_NODES + j0 + c0;
        __half* Psb = Ps + buf * (BI * PSS);

#pragma unroll
        for (int rb = 0; rb < 32; rb += 8) {
            int2 av[8];
#pragma unroll
            for (int u = 0; u < 8; u++)
                av[u] = __ldg((const int2*)(adjp + (size_t)(rb + u) * N_NODES));
#pragma unroll
            for (int u = 0; u < 8; u++) {
                int row = rhalf * 32 + rb + u;
                float4 R = rowc[row];                    // broadcast LDS.128
                bool p0 = C0.x > R.x;                    // fj > -fi
                bool p1 = C1.x > R.x;
                float v0 = (p0 ? R.y : R.z) * (p0 ? C0.y : C0.z);
                float v1 = (p1 ? R.y : R.z) * (p1 ? C1.y : C1.z);
                v0 = av[u].x > 0 ? v0 : 0.f;
                v1 = av[u].y > 0 ? v1 : 0.f;
                *(__half2*)&Psb[row * PSS + c0] = __floats2half2_rn(v0, v1);
            }
        }
        __syncthreads();   // single barrier: double buffers remove the post-MMA one

        // ---- MMA: C[16 x 72] += P[16 x 128] @ V[128 x 72] per warp ----
        uint32_t abase = ps_u + buf * PS_BYTES + a_off;
        uint32_t vbase = vs_u + buf * VS_BYTES;
#pragma unroll
        for (int kk = 0; kk < BJ / 16; kk++) {
            uint32_t a0, a1, a2, a3;
            asm volatile("ldmatrix.sync.aligned.m8n8.x4.shared.b16 {%0,%1,%2,%3}, [%4];"
                         : "=r"(a0), "=r"(a1), "=r"(a2), "=r"(a3)
                         : "r"(abase + kk * 32));
            uint32_t brow = vbase + 2u * ((kk * 16 + (lane & 15)) * NV);
#pragma unroll
            for (int ng = 0; ng < 9; ng++) {
                uint32_t b0, b1;
                asm volatile("ldmatrix.sync.aligned.m8n8.x2.trans.shared.b16 {%0,%1}, [%2];"
                             : "=r"(b0), "=r"(b1) : "r"(brow + ng * 16));
                asm volatile("mma.sync.aligned.m16n8k16.row.col.f32.f16.f16.f32 "
                             "{%0,%1,%2,%3}, {%4,%5,%6,%7}, {%8,%9}, {%0,%1,%2,%3};"
                             : "+f"(c[ng][0]), "+f"(c[ng][1]), "+f"(c[ng][2]), "+f"(c[ng][3])
                             : "r"(a0), "r"(a1), "r"(a2), "r"(a3), "r"(b0), "r"(b1));
            }
        }
    }

    // ---- store partials (numerator cols 0..63, denom col 64) ----
    float* pp = g_part + ((size_t)(blockIdx.y * IBLOCKS + blockIdx.x)) * (BI * NV);
    int r0 = m0 + (lane >> 2);
    int cb = (lane & 3) * 2;
#pragma unroll
    for (int ng = 0; ng < 9; ng++) {
        *(float2*)&pp[(size_t)r0 * NV + ng * 8 + cb]       = make_float2(c[ng][0], c[ng][1]);
        *(float2*)&pp[(size_t)(r0 + 8) * NV + ng * 8 + cb] = make_float2(c[ng][2], c[ng][3]);
    }
}

// ---------------------------------------------------------------------------
// Reduce: sum 4 split-partials, divide by denom (ones column), ELU, store.
// ---------------------------------------------------------------------------
__global__ __launch_bounds__(128) void reduce_kernel(float* __restrict__ out) {
    int tid = threadIdx.x;
    int row = blockIdx.x * 4 + (tid >> 5);
    int cp  = tid & 31;                 // column pair -> cols 2cp, 2cp+1

    size_t base = (size_t)row * NV;     // (ib*64 + r)*NV == row*NV globally
    float denom = 0.f, n0 = 0.f, n1 = 0.f;
#pragma unroll
    for (int s = 0; s < JSPLIT; s++) {
        const float* p = g_part + (size_t)s * IBLOCKS * BI * NV + base;
        denom += __ldg(&p[64]);
        float2 v = *(const float2*)(p + 2 * cp);
        n0 += v.x;
        n1 += v.y;
    }
    float inv = 1.0f / denom;
    float h0 = n0 * inv, h1 = n1 * inv;
    h0 = h0 > 0.f ? h0 : expm1f(h0);
    h1 = h1 > 0.f ? h1 : expm1f(h1);
    *(float2*)&out[(size_t)row * OUT_F + 2 * cp] = make_float2(h0, h1);
}

// ---------------------------------------------------------------------------
extern "C" void kernel_launch(void* const* d_in, const int* in_sizes, int n_in,
                              void* d_out, int out_size) {
    const float* x   = (const float*)d_in[0];   // [16384, 128] f32
    const int*   adj = (const int*)d_in[1];     // [16384, 16384] i32
    const float* w   = (const float*)d_in[2];   // [128, 64] f32
    const float* aw  = (const float*)d_in[3];   // [128, 1] f32
    float* out = (float*)d_out;                 // [16384, 64] f32

    cudaFuncSetAttribute(gat_main, cudaFuncAttributeMaxDynamicSharedMemorySize,
                         SMEM_TOTAL);

    wh_kernel<<<N_NODES / 32, 256>>>(x, w);
    f_kernel<<<N_NODES / 256, 256>>>(aw);
    gat_main<<<dim3(IBLOCKS, JSPLIT), 128, SMEM_TOTAL>>>(adj);
    reduce_kernel<<<N_NODES / 4, 128>>>(out);
}

// round 6
// speedup vs baseline: 2.5077x; 1.0800x over previous
#include <cuda_runtime.h>
#include <cuda_fp16.h>
#include <cstdint>
#include <cstddef>

#define N_NODES 16384
#define IN_F    128
#define OUT_F   64
#define NV      72      // V cols: 64 feats + ones col (denominator) + 7 pad
#define BI      64      // rows per CTA
#define BJ      128     // j-tile width
#define PSS     136     // P row stride (halves), conflict-free for ldmatrix
#define JSPLIT  8
#define JTILES  (N_NODES / JSPLIT / BJ)   // 16
#define IBLOCKS (N_NODES / BI)            // 256

#define PS_BYTES (BI * PSS * 2)           // 17408
#define VS_BYTES (BJ * NV * 2)            // 18432
#define SMEM_TOTAL (2 * PS_BYTES + 2 * VS_BYTES + BI * 16)  // 72704

// Scratch (device globals: allocation-free rule)
__device__ __align__(16) float  g_Wh[N_NODES * OUT_F];
__device__ __align__(16) __half g_V [N_NODES * NV];
__device__ __align__(16) float4 g_rowc[N_NODES];   // {-fi, e^fi, e^{.02fi}, 0}
__device__ __align__(16) float4 g_colc[N_NODES];   // { fj, e^fj, e^{.02fj}, 0}
__device__ __align__(16) float  g_part[(size_t)JSPLIT * IBLOCKS * BI * NV];  // 37.7MB

// ---------------------------------------------------------------------------
// Kernel A: Wh = x @ W (fp32) + fp16 V with ones column
// ---------------------------------------------------------------------------
__global__ __launch_bounds__(256) void wh_kernel(const float* __restrict__ x,
                                                 const float* __restrict__ w) {
    __shared__ float ws[IN_F * OUT_F];
    int tid = threadIdx.x;
    for (int t = tid; t < IN_F * OUT_F; t += 256) ws[t] = w[t];
    __syncthreads();

    int rl  = tid >> 3;
    int c0  = (tid & 7) * 8;
    int row = blockIdx.x * 32 + rl;

    float acc[8];
#pragma unroll
    for (int j = 0; j < 8; j++) acc[j] = 0.f;

    const float4* xr = (const float4*)(x + (size_t)row * IN_F);
#pragma unroll 8
    for (int q = 0; q < 32; q++) {
        float4 xv = __ldg(&xr[q]);
        int k = q * 4;
#pragma unroll
        for (int j = 0; j < 8; j++) acc[j] = fmaf(xv.x, ws[(k + 0) * OUT_F + c0 + j], acc[j]);
#pragma unroll
        for (int j = 0; j < 8; j++) acc[j] = fmaf(xv.y, ws[(k + 1) * OUT_F + c0 + j], acc[j]);
#pragma unroll
        for (int j = 0; j < 8; j++) acc[j] = fmaf(xv.z, ws[(k + 2) * OUT_F + c0 + j], acc[j]);
#pragma unroll
        for (int j = 0; j < 8; j++) acc[j] = fmaf(xv.w, ws[(k + 3) * OUT_F + c0 + j], acc[j]);
    }
#pragma unroll
    for (int j = 0; j < 8; j++) {
        g_Wh[(size_t)row * OUT_F + c0 + j] = acc[j];
        g_V[(size_t)row * NV + c0 + j]     = __float2half(acc[j]);
    }
    if ((tid & 7) == 0) {
        g_V[(size_t)row * NV + 64] = __float2half(1.0f);
#pragma unroll
        for (int t = 65; t < NV; t++) g_V[(size_t)row * NV + t] = __float2half(0.0f);
    }
}

// ---------------------------------------------------------------------------
// Kernel B: attention scalars + exp tables
// ---------------------------------------------------------------------------
__global__ __launch_bounds__(256) void f_kernel(const float* __restrict__ aw) {
    int r = blockIdx.x * blockDim.x + threadIdx.x;
    const float4* whr = (const float4*)(g_Wh + (size_t)r * OUT_F);
    float fi = 0.f, fj = 0.f;
#pragma unroll
    for (int q = 0; q < 16; q++) {
        float4 v = whr[q];
        fi += v.x * __ldg(&aw[q * 4 + 0]) + v.y * __ldg(&aw[q * 4 + 1])
            + v.z * __ldg(&aw[q * 4 + 2]) + v.w * __ldg(&aw[q * 4 + 3]);
        fj += v.x * __ldg(&aw[64 + q * 4 + 0]) + v.y * __ldg(&aw[64 + q * 4 + 1])
            + v.z * __ldg(&aw[64 + q * 4 + 2]) + v.w * __ldg(&aw[64 + q * 4 + 3]);
    }
    g_rowc[r] = make_float4(-fi, expf(fi), expf(0.02f * fi), 0.f);
    g_colc[r] = make_float4(fj,  expf(fj), expf(0.02f * fj), 0.f);
}

// ---------------------------------------------------------------------------
// Per-warp MMA over one buffered tile: C[16x72] += P[16x128] @ V[128x72]
// ---------------------------------------------------------------------------
__device__ __forceinline__ void run_mma(uint32_t abase, uint32_t vbase, int lane,
                                        float (&c)[9][4]) {
#pragma unroll
    for (int kk = 0; kk < BJ / 16; kk++) {
        uint32_t a0, a1, a2, a3;
        asm volatile("ldmatrix.sync.aligned.m8n8.x4.shared.b16 {%0,%1,%2,%3}, [%4];"
                     : "=r"(a0), "=r"(a1), "=r"(a2), "=r"(a3)
                     : "r"(abase + kk * 32));
        uint32_t brow = vbase + 2u * ((kk * 16 + (lane & 15)) * NV);
#pragma unroll
        for (int ng = 0; ng < 9; ng++) {
            uint32_t b0, b1;
            asm volatile("ldmatrix.sync.aligned.m8n8.x2.trans.shared.b16 {%0,%1}, [%2];"
                         : "=r"(b0), "=r"(b1) : "r"(brow + ng * 16));
            asm volatile("mma.sync.aligned.m16n8k16.row.col.f32.f16.f16.f32 "
                         "{%0,%1,%2,%3}, {%4,%5,%6,%7}, {%8,%9}, {%0,%1,%2,%3};"
                         : "+f"(c[ng][0]), "+f"(c[ng][1]), "+f"(c[ng][2]), "+f"(c[ng][3])
                         : "r"(a0), "r"(a1), "r"(a2), "r"(a3), "r"(b0), "r"(b1));
        }
    }
}

// ---------------------------------------------------------------------------
// Main fused kernel, software-pipelined:
//   iter t: load V(t), issue ALL adj(t) loads, MMA(t-1) [hides adj latency],
//           compute P(t), barrier.
// Double-buffered Ps/Vs, one barrier per tile, no MUFU in hot loop.
// ---------------------------------------------------------------------------
__global__ __launch_bounds__(128, 3) void gat_main(const int* __restrict__ adj) {
    extern __shared__ __align__(16) char sm[];
    __half* Ps = (__half*)sm;
    __half* Vs = (__half*)(sm + 2 * PS_BYTES);
    float4* rowc = (float4*)(sm + 2 * PS_BYTES + 2 * VS_BYTES);

    int tid  = threadIdx.x;
    int lane = tid & 31;
    int warp = tid >> 5;
    int i0    = blockIdx.x * BI;
    int jbase = blockIdx.y * (N_NODES / JSPLIT);

    if (tid < BI) rowc[tid] = g_rowc[i0 + tid];
    __syncthreads();

    float c[9][4];
#pragma unroll
    for (int ng = 0; ng < 9; ng++)
#pragma unroll
        for (int q = 0; q < 4; q++) c[ng][q] = 0.f;

    // producer mapping: 2 cols x 32 rows per thread
    int rhalf = tid >> 6;
    int c0    = (tid & 63) * 2;

    uint32_t ps_u = (uint32_t)__cvta_generic_to_shared(Ps);
    uint32_t vs_u = (uint32_t)__cvta_generic_to_shared(Vs);
    int m0 = warp * 16;
    uint32_t a_off = 2u * ((m0 + (lane & 15)) * PSS + (lane >> 4) * 8);

#pragma unroll 1
    for (int t = 0; t < JTILES; t++) {
        int j0  = jbase + t * BJ;
        int buf = t & 1;

        // ---- V tile into buf (L2-resident, short latency) ----
        {
            const uint4* vsrc = (const uint4*)(g_V + (size_t)j0 * NV);
            uint4* vdst = (uint4*)(Vs + buf * (BJ * NV));
#pragma unroll
            for (int q = 0; q < 9; q++)
                vdst[tid + q * 128] = vsrc[tid + q * 128];
        }

        // ---- issue ALL adj loads for tile t (latency drains under MMA) ----
        float4 C0 = __ldg(&g_colc[j0 + c0]);
        float4 C1 = __ldg(&g_colc[j0 + c0 + 1]);
        const int* adjp = adj + (size_t)(i0 + rhalf * 32) * N_NODES + j0 + c0;
        int2 av[32];
#pragma unroll
        for (int u = 0; u < 32; u++)
            av[u] = __ldg((const int2*)(adjp + (size_t)u * N_NODES));

        // ---- MMA for previous tile while adj loads are in flight ----
        if (t > 0)
            run_mma(ps_u + (buf ^ 1) * PS_BYTES + a_off,
                    vs_u + (buf ^ 1) * VS_BYTES, lane, c);

        // ---- P tile: select-multiply, no exp ----
        __half* Psb = Ps + buf * (BI * PSS);
#pragma unroll
        for (int u = 0; u < 32; u++) {
            int row = rhalf * 32 + u;
            float4 R = rowc[row];                    // broadcast LDS.128
            bool p0 = C0.x > R.x;                    // fj > -fi
            bool p1 = C1.x > R.x;
            float v0 = (p0 ? R.y : R.z) * (p0 ? C0.y : C0.z);
            float v1 = (p1 ? R.y : R.z) * (p1 ? C1.y : C1.z);
            v0 = av[u].x > 0 ? v0 : 0.f;
            v1 = av[u].y > 0 ? v1 : 0.f;
            *(__half2*)&Psb[row * PSS + c0] = __floats2half2_rn(v0, v1);
        }
        __syncthreads();   // single barrier per tile (double buffers cover the rest)
    }

    // ---- drain: MMA for the last tile ----
    {
        int buf = (JTILES - 1) & 1;
        run_mma(ps_u + buf * PS_BYTES + a_off, vs_u + buf * VS_BYTES, lane, c);
    }

    // ---- store partials (numerator cols 0..63, denom col 64) ----
    float* pp = g_part + ((size_t)(blockIdx.y * IBLOCKS + blockIdx.x)) * (BI * NV);
    int r0 = m0 + (lane >> 2);
    int cb = (lane & 3) * 2;
#pragma unroll
    for (int ng = 0; ng < 9; ng++) {
        *(float2*)&pp[(size_t)r0 * NV + ng * 8 + cb]       = make_float2(c[ng][0], c[ng][1]);
        *(float2*)&pp[(size_t)(r0 + 8) * NV + ng * 8 + cb] = make_float2(c[ng][2], c[ng][3]);
    }
}

// ---------------------------------------------------------------------------
// Reduce: sum 8 split-partials, divide by denom (ones column), ELU, store.
// ---------------------------------------------------------------------------
__global__ __launch_bounds__(128) void reduce_kernel(float* __restrict__ out) {
    int tid = threadIdx.x;
    int row = blockIdx.x * 4 + (tid >> 5);
    int cp  = tid & 31;                 // column pair -> cols 2cp, 2cp+1

    size_t base = (size_t)row * NV;
    float denom = 0.f, n0 = 0.f, n1 = 0.f;
#pragma unroll
    for (int s = 0; s < JSPLIT; s++) {
        const float* p = g_part + (size_t)s * IBLOCKS * BI * NV + base;
        denom += __ldg(&p[64]);
        float2 v = *(const float2*)(p + 2 * cp);
        n0 += v.x;
        n1 += v.y;
    }
    float inv = 1.0f / denom;
    float h0 = n0 * inv, h1 = n1 * inv;
    h0 = h0 > 0.f ? h0 : expm1f(h0);
    h1 = h1 > 0.f ? h1 : expm1f(h1);
    *(float2*)&out[(size_t)row * OUT_F + 2 * cp] = make_float2(h0, h1);
}

// ---------------------------------------------------------------------------
extern "C" void kernel_launch(void* const* d_in, const int* in_sizes, int n_in,
                              void* d_out, int out_size) {
    const float* x   = (const float*)d_in[0];   // [16384, 128] f32
    const int*   adj = (const int*)d_in[1];     // [16384, 16384] i32
    const float* w   = (const float*)d_in[2];   // [128, 64] f32
    const float* aw  = (const float*)d_in[3];   // [128, 1] f32
    float* out = (float*)d_out;                 // [16384, 64] f32

    cudaFuncSetAttribute(gat_main, cudaFuncAttributeMaxDynamicSharedMemorySize,
                         SMEM_TOTAL);

    wh_kernel<<<N_NODES / 32, 256>>>(x, w);
    f_kernel<<<N_NODES / 256, 256>>>(aw);
    gat_main<<<dim3(IBLOCKS, JSPLIT), 128, SMEM_TOTAL>>>(adj);
    reduce_kernel<<<N_NODES / 4, 128>>>(out);
}

// round 8
// speedup vs baseline: 2.5529x; 1.0180x over previous
#include <cuda_runtime.h>
#include <cuda_fp16.h>
#include <cstdint>
#include <cstddef>

#define N_NODES 16384
#define IN_F    128
#define OUT_F   64
#define NV      72      // V cols: 64 feats + ones col (denominator) + 7 pad
#define BI      128     // rows per CTA
#define BJ      128     // j-tile width
#define PSS     136     // P row stride (halves), conflict-free for ldmatrix
#define JSPLIT  16
#define JTILES  (N_NODES / JSPLIT / BJ)   // 8
#define IBLOCKS (N_NODES / BI)            // 128

#define PS_BYTES (BI * PSS * 2)           // 34816
#define VS_BYTES (BJ * NV * 2)            // 18432
#define SMEM_TOTAL (2 * PS_BYTES + 2 * VS_BYTES + BI * 16)  // 108544

// Scratch (device globals: allocation-free rule)
__device__ __align__(16) float  g_Wh[N_NODES * OUT_F];
__device__ __align__(16) __half g_V [N_NODES * NV];
__device__ __align__(16) float4 g_rowc[N_NODES];   // {-fi, e^fi, e^{.02fi}, 0}
__device__ __align__(16) float4 g_colc[N_NODES];   // { fj, e^fj, e^{.02fj}, 0}
__device__ __align__(16) float  g_part[(size_t)JSPLIT * N_NODES * NV];  // 75.5MB

// ---------------------------------------------------------------------------
// Kernel A: Wh = x @ W (fp32) + fp16 V with ones column
// ---------------------------------------------------------------------------
__global__ __launch_bounds__(256) void wh_kernel(const float* __restrict__ x,
                                                 const float* __restrict__ w) {
    __shared__ float ws[IN_F * OUT_F];
    int tid = threadIdx.x;
    for (int t = tid; t < IN_F * OUT_F; t += 256) ws[t] = w[t];
    __syncthreads();

    int rl  = tid >> 3;
    int c0  = (tid & 7) * 8;
    int row = blockIdx.x * 32 + rl;

    float acc[8];
#pragma unroll
    for (int j = 0; j < 8; j++) acc[j] = 0.f;

    const float4* xr = (const float4*)(x + (size_t)row * IN_F);
#pragma unroll 8
    for (int q = 0; q < 32; q++) {
        float4 xv = __ldg(&xr[q]);
        int k = q * 4;
#pragma unroll
        for (int j = 0; j < 8; j++) acc[j] = fmaf(xv.x, ws[(k + 0) * OUT_F + c0 + j], acc[j]);
#pragma unroll
        for (int j = 0; j < 8; j++) acc[j] = fmaf(xv.y, ws[(k + 1) * OUT_F + c0 + j], acc[j]);
#pragma unroll
        for (int j = 0; j < 8; j++) acc[j] = fmaf(xv.z, ws[(k + 2) * OUT_F + c0 + j], acc[j]);
#pragma unroll
        for (int j = 0; j < 8; j++) acc[j] = fmaf(xv.w, ws[(k + 3) * OUT_F + c0 + j], acc[j]);
    }
#pragma unroll
    for (int j = 0; j < 8; j++) {
        g_Wh[(size_t)row * OUT_F + c0 + j] = acc[j];
        g_V[(size_t)row * NV + c0 + j]     = __float2half(acc[j]);
    }
    if ((tid & 7) == 0) {
        g_V[(size_t)row * NV + 64] = __float2half(1.0f);
#pragma unroll
        for (int t = 65; t < NV; t++) g_V[(size_t)row * NV + t] = __float2half(0.0f);
    }
}

// ---------------------------------------------------------------------------
// Kernel B: attention scalars + exp tables
// ---------------------------------------------------------------------------
__global__ __launch_bounds__(256) void f_kernel(const float* __restrict__ aw) {
    int r = blockIdx.x * blockDim.x + threadIdx.x;
    const float4* whr = (const float4*)(g_Wh + (size_t)r * OUT_F);
    float fi = 0.f, fj = 0.f;
#pragma unroll
    for (int q = 0; q < 16; q++) {
        float4 v = whr[q];
        fi += v.x * __ldg(&aw[q * 4 + 0]) + v.y * __ldg(&aw[q * 4 + 1])
            + v.z * __ldg(&aw[q * 4 + 2]) + v.w * __ldg(&aw[q * 4 + 3]);
        fj += v.x * __ldg(&aw[64 + q * 4 + 0]) + v.y * __ldg(&aw[64 + q * 4 + 1])
            + v.z * __ldg(&aw[64 + q * 4 + 2]) + v.w * __ldg(&aw[64 + q * 4 + 3]);
    }
    g_rowc[r] = make_float4(-fi, expf(fi), expf(0.02f * fi), 0.f);
    g_colc[r] = make_float4(fj,  expf(fj), expf(0.02f * fj), 0.f);
}

// ---------------------------------------------------------------------------
// Half-tile MMA (4 k-steps): per warp C[2][9][4] over M=32 (two m16 tiles).
// B loaded with x4.trans (two n-tiles per LDSM), amortized across both m-tiles.
// ---------------------------------------------------------------------------
__device__ __forceinline__ void mma_half(uint32_t abase0, uint32_t abase1,
                                         uint32_t vbase, int lane,
                                         float (&c)[2][9][4], int kk0) {
#pragma unroll
    for (int kk = kk0; kk < kk0 + 4; kk++) {
        uint32_t A[2][4];
        asm volatile("ldmatrix.sync.aligned.m8n8.x4.shared.b16 {%0,%1,%2,%3}, [%4];"
                     : "=r"(A[0][0]), "=r"(A[0][1]), "=r"(A[0][2]), "=r"(A[0][3])
                     : "r"(abase0 + kk * 32));
        asm volatile("ldmatrix.sync.aligned.m8n8.x4.shared.b16 {%0,%1,%2,%3}, [%4];"
                     : "=r"(A[1][0]), "=r"(A[1][1]), "=r"(A[1][2]), "=r"(A[1][3])
                     : "r"(abase1 + kk * 32));
        uint32_t B[9][2];
        uint32_t brow = vbase + 2u * ((kk * 16 + (lane & 15)) * NV) + ((lane >> 4) << 4);
#pragma unroll
        for (int gp = 0; gp < 4; gp++) {
            asm volatile("ldmatrix.sync.aligned.m8n8.x4.trans.shared.b16 {%0,%1,%2,%3}, [%4];"
                         : "=r"(B[2 * gp][0]), "=r"(B[2 * gp][1]),
                           "=r"(B[2 * gp + 1][0]), "=r"(B[2 * gp + 1][1])
                         : "r"(brow + gp * 32));
        }
        asm volatile("ldmatrix.sync.aligned.m8n8.x2.trans.shared.b16 {%0,%1}, [%2];"
                     : "=r"(B[8][0]), "=r"(B[8][1])
                     : "r"(vbase + 2u * ((kk * 16 + (lane & 15)) * NV) + 128));
#pragma unroll
        for (int m = 0; m < 2; m++)
#pragma unroll
            for (int ng = 0; ng < 9; ng++)
                asm volatile("mma.sync.aligned.m16n8k16.row.col.f32.f16.f16.f32 "
                             "{%0,%1,%2,%3}, {%4,%5,%6,%7}, {%8,%9}, {%0,%1,%2,%3};"
                             : "+f"(c[m][ng][0]), "+f"(c[m][ng][1]),
                               "+f"(c[m][ng][2]), "+f"(c[m][ng][3])
                             : "r"(A[m][0]), "r"(A[m][1]), "r"(A[m][2]), "r"(A[m][3]),
                               "r"(B[ng][0]), "r"(B[ng][1]));
    }
}

// ---------------------------------------------------------------------------
// Main fused kernel: M=128 per CTA, software-pipelined, double-buffered,
// one barrier per tile. adj loads in two batches interleaved with MMA halves.
// ---------------------------------------------------------------------------
__global__ __launch_bounds__(128, 2) void gat_main(const int* __restrict__ adj) {
    extern __shared__ __align__(16) char sm[];
    __half* Ps = (__half*)sm;
    __half* Vs = (__half*)(sm + 2 * PS_BYTES);
    float4* rowc = (float4*)(sm + 2 * PS_BYTES + 2 * VS_BYTES);

    int tid  = threadIdx.x;
    int lane = tid & 31;
    int warp = tid >> 5;
    int i0    = blockIdx.x * BI;
    int jbase = blockIdx.y * (N_NODES / JSPLIT);

    rowc[tid] = g_rowc[i0 + tid];
    __syncthreads();

    float c[2][9][4];
#pragma unroll
    for (int m = 0; m < 2; m++)
#pragma unroll
        for (int ng = 0; ng < 9; ng++)
#pragma unroll
            for (int q = 0; q < 4; q++) c[m][ng][q] = 0.f;

    // producer mapping: 2 cols x 64 rows per thread (two 32-row batches)
    int rhalf = tid >> 6;          // rows rhalf*64 .. +64
    int c0    = (tid & 63) * 2;

    uint32_t ps_u = (uint32_t)__cvta_generic_to_shared(Ps);
    uint32_t vs_u = (uint32_t)__cvta_generic_to_shared(Vs);
    int m0 = warp * 32;
    uint32_t a_off0 = 2u * ((m0 + (lane & 15)) * PSS + (lane >> 4) * 8);
    uint32_t a_off1 = 2u * ((m0 + 16 + (lane & 15)) * PSS + (lane >> 4) * 8);

#pragma unroll 1
    for (int t = 0; t < JTILES; t++) {
        int j0  = jbase + t * BJ;
        int buf = t & 1;
        uint32_t pab0 = ps_u + (buf ^ 1) * PS_BYTES + a_off0;
        uint32_t pab1 = ps_u + (buf ^ 1) * PS_BYTES + a_off1;
        uint32_t pvb  = vs_u + (buf ^ 1) * VS_BYTES;

        // ---- V tile into buf ----
        {
            const uint4* vsrc = (const uint4*)(g_V + (size_t)j0 * NV);
            uint4* vdst = (uint4*)(Vs + buf * (BJ * NV));
#pragma unroll
            for (int q = 0; q < 9; q++)
                vdst[tid + q * 128] = vsrc[tid + q * 128];
        }

        float4 C0 = __ldg(&g_colc[j0 + c0]);
        float4 C1 = __ldg(&g_colc[j0 + c0 + 1]);
        const int* adjp = adj + (size_t)(i0 + rhalf * 64) * N_NODES + j0 + c0;
        __half* Psb = Ps + buf * (BI * PSS);

        // ---- batch LO: issue 32 adj loads, MMA(t-1) kk 0..3 under them ----
        int2 av[32];
#pragma unroll
        for (int u = 0; u < 32; u++)
            av[u] = __ldg((const int2*)(adjp + (size_t)u * N_NODES));

        if (t > 0) mma_half(pab0, pab1, pvb, lane, c, 0);

#pragma unroll
        for (int u = 0; u < 32; u++) {
            int row = rhalf * 64 + u;
            float4 R = rowc[row];
            bool s0 = C0.x > R.x;
            bool s1 = C1.x > R.x;
            float v0 = (s0 ? R.y : R.z) * (s0 ? C0.y : C0.z);
            float v1 = (s1 ? R.y : R.z) * (s1 ? C1.y : C1.z);
            v0 = av[u].x > 0 ? v0 : 0.f;
            v1 = av[u].y > 0 ? v1 : 0.f;
            *(__half2*)&Psb[row * PSS + c0] = __floats2half2_rn(v0, v1);
        }

        // ---- batch HI: issue next 32 adj loads, MMA(t-1) kk 4..7 ----
#pragma unroll
        for (int u = 0; u < 32; u++)
            av[u] = __ldg((const int2*)(adjp + (size_t)(32 + u) * N_NODES));

        if (t > 0) mma_half(pab0, pab1, pvb, lane, c, 4);

#pragma unroll
        for (int u = 0; u < 32; u++) {
            int row = rhalf * 64 + 32 + u;
            float4 R = rowc[row];
            bool s0 = C0.x > R.x;
            bool s1 = C1.x > R.x;
            float v0 = (s0 ? R.y : R.z) * (s0 ? C0.y : C0.z);
            float v1 = (s1 ? R.y : R.z) * (s1 ? C1.y : C1.z);
            v0 = av[u].x > 0 ? v0 : 0.f;
            v1 = av[u].y > 0 ? v1 : 0.f;
            *(__half2*)&Psb[row * PSS + c0] = __floats2half2_rn(v0, v1);
        }
        __syncthreads();   // single barrier per tile
    }

    // ---- drain: MMA for the last tile ----
    {
        int buf = (JTILES - 1) & 1;
        mma_half(ps_u + buf * PS_BYTES + a_off0, ps_u + buf * PS_BYTES + a_off1,
                 vs_u + buf * VS_BYTES, lane, c, 0);
        mma_half(ps_u + buf * PS_BYTES + a_off0, ps_u + buf * PS_BYTES + a_off1,
                 vs_u + buf * VS_BYTES, lane, c, 4);
    }

    // ---- store partials (numerator cols 0..63, denom col 64) ----
    float* pp = g_part + ((size_t)blockIdx.y * N_NODES + i0) * NV;
    int r0 = m0 + (lane >> 2);
    int cb = (lane & 3) * 2;
#pragma unroll
    for (int m = 0; m < 2; m++)
#pragma unroll
        for (int ng = 0; ng < 9; ng++) {
            *(float2*)&pp[(size_t)(r0 + m * 16) * NV + ng * 8 + cb] =
                make_float2(c[m][ng][0], c[m][ng][1]);
            *(float2*)&pp[(size_t)(r0 + m * 16 + 8) * NV + ng * 8 + cb] =
                make_float2(c[m][ng][2], c[m][ng][3]);
        }
}

// ---------------------------------------------------------------------------
// Reduce: sum 16 split-partials, divide by denom (col 64), ELU, store.
// ---------------------------------------------------------------------------
__global__ __launch_bounds__(128) void reduce_kernel(float* __restrict__ out) {
    int tid = threadIdx.x;
    int row = blockIdx.x * 4 + (tid >> 5);
    int cp  = tid & 31;

    size_t base = (size_t)row * NV;
    float denom = 0.f, n0 = 0.f, n1 = 0.f;
#pragma unroll
    for (int s = 0; s < JSPLIT; s++) {
        const float* p = g_part + (size_t)s * N_NODES * NV + base;
        denom += __ldg(&p[64]);
        float2 v = *(const float2*)(p + 2 * cp);
        n0 += v.x;
        n1 += v.y;
    }
    float inv = 1.0f / denom;
    float h0 = n0 * inv, h1 = n1 * inv;
    h0 = h0 > 0.f ? h0 : expm1f(h0);
    h1 = h1 > 0.f ? h1 : expm1f(h1);
    *(float2*)&out[(size_t)row * OUT_F + 2 * cp] = make_float2(h0, h1);
}

// ---------------------------------------------------------------------------
extern "C" void kernel_launch(void* const* d_in, const int* in_sizes, int n_in,
                              void* d_out, int out_size) {
    const float* x   = (const float*)d_in[0];   // [16384, 128] f32
    const int*   adj = (const int*)d_in[1];     // [16384, 16384] i32
    const float* w   = (const float*)d_in[2];   // [128, 64] f32
    const float* aw  = (const float*)d_in[3];   // [128, 1] f32
    float* out = (float*)d_out;                 // [16384, 64] f32

    cudaFuncSetAttribute(gat_main, cudaFuncAttributeMaxDynamicSharedMemorySize,
                         SMEM_TOTAL);

    wh_kernel<<<N_NODES / 32, 256>>>(x, w);
    f_kernel<<<N_NODES / 256, 256>>>(aw);
    gat_main<<<dim3(IBLOCKS, JSPLIT), 128, SMEM_TOTAL>>>(adj);
    reduce_kernel<<<N_NODES / 4, 128>>>(out);
}

// round 9
// speedup vs baseline: 3.2578x; 1.2761x over previous
#include <cuda_runtime.h>
#include <cuda_fp16.h>
#include <cstdint>
#include <cstddef>

#define N_NODES 16384
#define IN_F    128
#define OUT_F   64
#define NV      72      // V cols: 64 feats + ones col (denominator) + 7 pad
#define BI      128     // rows per CTA
#define BJ      128     // j-tile width
#define PSS     136     // P row stride (halves), conflict-free for ldmatrix
#define JSPLIT  16
#define JTILES  (N_NODES / JSPLIT / BJ)   // 8
#define IBLOCKS (N_NODES / BI)            // 128

#define PS_BYTES (BI * PSS * 2)           // 34816
#define VS_BYTES (BJ * NV * 2)            // 18432
#define SMEM_TOTAL (2 * PS_BYTES + 2 * VS_BYTES + BI * 16)  // 108544

// Scratch (device globals: allocation-free rule)
__device__ __align__(16) float  g_Wh[N_NODES * OUT_F];
__device__ __align__(16) __half g_V [N_NODES * NV];
__device__ __align__(16) float4 g_rowc[N_NODES];   // {-fi, e^fi, e^{.02fi}, 0}
__device__ __align__(16) float4 g_colc[N_NODES];   // { fj, e^fj, e^{.02fj}, 0}
__device__ __align__(16) float  g_part[(size_t)JSPLIT * N_NODES * NV];  // 75.5MB

// ---------------------------------------------------------------------------
// Kernel A: Wh = x @ W (fp32) + fp16 V with ones column
// ---------------------------------------------------------------------------
__global__ __launch_bounds__(256) void wh_kernel(const float* __restrict__ x,
                                                 const float* __restrict__ w) {
    __shared__ float ws[IN_F * OUT_F];
    int tid = threadIdx.x;
    for (int t = tid; t < IN_F * OUT_F; t += 256) ws[t] = w[t];
    __syncthreads();

    int rl  = tid >> 3;
    int c0  = (tid & 7) * 8;
    int row = blockIdx.x * 32 + rl;

    float acc[8];
#pragma unroll
    for (int j = 0; j < 8; j++) acc[j] = 0.f;

    const float4* xr = (const float4*)(x + (size_t)row * IN_F);
#pragma unroll 8
    for (int q = 0; q < 32; q++) {
        float4 xv = __ldg(&xr[q]);
        int k = q * 4;
#pragma unroll
        for (int j = 0; j < 8; j++) acc[j] = fmaf(xv.x, ws[(k + 0) * OUT_F + c0 + j], acc[j]);
#pragma unroll
        for (int j = 0; j < 8; j++) acc[j] = fmaf(xv.y, ws[(k + 1) * OUT_F + c0 + j], acc[j]);
#pragma unroll
        for (int j = 0; j < 8; j++) acc[j] = fmaf(xv.z, ws[(k + 2) * OUT_F + c0 + j], acc[j]);
#pragma unroll
        for (int j = 0; j < 8; j++) acc[j] = fmaf(xv.w, ws[(k + 3) * OUT_F + c0 + j], acc[j]);
    }
#pragma unroll
    for (int j = 0; j < 8; j++) {
        g_Wh[(size_t)row * OUT_F + c0 + j] = acc[j];
        g_V[(size_t)row * NV + c0 + j]     = __float2half(acc[j]);
    }
    if ((tid & 7) == 0) {
        g_V[(size_t)row * NV + 64] = __float2half(1.0f);
#pragma unroll
        for (int t = 65; t < NV; t++) g_V[(size_t)row * NV + t] = __float2half(0.0f);
    }
}

// ---------------------------------------------------------------------------
// Kernel B: attention scalars + exp tables
// ---------------------------------------------------------------------------
__global__ __launch_bounds__(256) void f_kernel(const float* __restrict__ aw) {
    int r = blockIdx.x * blockDim.x + threadIdx.x;
    const float4* whr = (const float4*)(g_Wh + (size_t)r * OUT_F);
    float fi = 0.f, fj = 0.f;
#pragma unroll
    for (int q = 0; q < 16; q++) {
        float4 v = whr[q];
        fi += v.x * __ldg(&aw[q * 4 + 0]) + v.y * __ldg(&aw[q * 4 + 1])
            + v.z * __ldg(&aw[q * 4 + 2]) + v.w * __ldg(&aw[q * 4 + 3]);
        fj += v.x * __ldg(&aw[64 + q * 4 + 0]) + v.y * __ldg(&aw[64 + q * 4 + 1])
            + v.z * __ldg(&aw[64 + q * 4 + 2]) + v.w * __ldg(&aw[64 + q * 4 + 3]);
    }
    g_rowc[r] = make_float4(-fi, expf(fi), expf(0.02f * fi), 0.f);
    g_colc[r] = make_float4(fj,  expf(fj), expf(0.02f * fj), 0.f);
}

// ---------------------------------------------------------------------------
// Half-tile MMA (4 k-steps), per warp M=16: C[9][4] += P[16xk] @ V[kx72].
// B loaded with x4.trans (two n-tiles per LDSM).
// ---------------------------------------------------------------------------
__device__ __forceinline__ void mma_half(uint32_t abase, uint32_t vbase, int lane,
                                         float (&c)[9][4], int kk0) {
#pragma unroll
    for (int kk = kk0; kk < kk0 + 4; kk++) {
        uint32_t A[4];
        asm volatile("ldmatrix.sync.aligned.m8n8.x4.shared.b16 {%0,%1,%2,%3}, [%4];"
                     : "=r"(A[0]), "=r"(A[1]), "=r"(A[2]), "=r"(A[3])
                     : "r"(abase + kk * 32));
        uint32_t B[9][2];
        uint32_t brow = vbase + 2u * ((kk * 16 + (lane & 15)) * NV) + ((lane >> 4) << 4);
#pragma unroll
        for (int gp = 0; gp < 4; gp++) {
            asm volatile("ldmatrix.sync.aligned.m8n8.x4.trans.shared.b16 {%0,%1,%2,%3}, [%4];"
                         : "=r"(B[2 * gp][0]), "=r"(B[2 * gp][1]),
                           "=r"(B[2 * gp + 1][0]), "=r"(B[2 * gp + 1][1])
                         : "r"(brow + gp * 32));
        }
        asm volatile("ldmatrix.sync.aligned.m8n8.x2.trans.shared.b16 {%0,%1}, [%2];"
                     : "=r"(B[8][0]), "=r"(B[8][1])
                     : "r"(vbase + 2u * ((kk * 16 + (lane & 15)) * NV) + 128));
#pragma unroll
        for (int ng = 0; ng < 9; ng++)
            asm volatile("mma.sync.aligned.m16n8k16.row.col.f32.f16.f16.f32 "
                         "{%0,%1,%2,%3}, {%4,%5,%6,%7}, {%8,%9}, {%0,%1,%2,%3};"
                         : "+f"(c[ng][0]), "+f"(c[ng][1]), "+f"(c[ng][2]), "+f"(c[ng][3])
                         : "r"(A[0]), "r"(A[1]), "r"(A[2]), "r"(A[3]),
                           "r"(B[ng][0]), "r"(B[ng][1]));
    }
}

// ---------------------------------------------------------------------------
// Main fused kernel: 256 threads (8 warps, M=16 each), 2 CTAs/SM -> 4 warps
// per SMSP for stall coverage. Double-buffered, one barrier per tile, adj
// loads in two 16-row batches each covered by an MMA half.
// ---------------------------------------------------------------------------
__global__ __launch_bounds__(256, 2) void gat_main(const int* __restrict__ adj) {
    extern __shared__ __align__(16) char sm[];
    __half* Ps = (__half*)sm;
    __half* Vs = (__half*)(sm + 2 * PS_BYTES);
    float4* rowc = (float4*)(sm + 2 * PS_BYTES + 2 * VS_BYTES);

    int tid  = threadIdx.x;
    int lane = tid & 31;
    int warp = tid >> 5;
    int i0    = blockIdx.x * BI;
    int jbase = blockIdx.y * (N_NODES / JSPLIT);

    if (tid < BI) rowc[tid] = g_rowc[i0 + tid];
    __syncthreads();

    float c[9][4];
#pragma unroll
    for (int ng = 0; ng < 9; ng++)
#pragma unroll
        for (int q = 0; q < 4; q++) c[ng][q] = 0.f;

    // producer mapping: 1 col-pair x 32 rows per thread (two 16-row batches)
    int rq = tid >> 6;             // 0..3 -> rows rq*32 .. +32
    int c0 = (tid & 63) * 2;

    uint32_t ps_u = (uint32_t)__cvta_generic_to_shared(Ps);
    uint32_t vs_u = (uint32_t)__cvta_generic_to_shared(Vs);
    int m0 = warp * 16;
    uint32_t a_off = 2u * ((m0 + (lane & 15)) * PSS + (lane >> 4) * 8);

#pragma unroll 1
    for (int t = 0; t < JTILES; t++) {
        int j0  = jbase + t * BJ;
        int buf = t & 1;
        uint32_t pab = ps_u + (buf ^ 1) * PS_BYTES + a_off;
        uint32_t pvb = vs_u + (buf ^ 1) * VS_BYTES;

        // ---- V tile into buf (1152 uint4 over 256 threads) ----
        {
            const uint4* vsrc = (const uint4*)(g_V + (size_t)j0 * NV);
            uint4* vdst = (uint4*)(Vs + buf * (BJ * NV));
#pragma unroll
            for (int q = 0; q < 5; q++) {
                int idx = tid + q * 256;
                if (idx < (BJ * NV) / 8) vdst[idx] = vsrc[idx];
            }
        }

        float4 C0 = __ldg(&g_colc[j0 + c0]);
        float4 C1 = __ldg(&g_colc[j0 + c0 + 1]);
        const int* adjp = adj + (size_t)(i0 + rq * 32) * N_NODES + j0 + c0;
        __half* Psb = Ps + buf * (BI * PSS);

        // ---- batch LO: 16 adj loads, MMA(t-1) kk 0..3 under them ----
        int2 av[16];
#pragma unroll
        for (int u = 0; u < 16; u++)
            av[u] = __ldg((const int2*)(adjp + (size_t)u * N_NODES));

        if (t > 0) mma_half(pab, pvb, lane, c, 0);

#pragma unroll
        for (int u = 0; u < 16; u++) {
            int row = rq * 32 + u;
            float4 R = rowc[row];
            bool s0 = C0.x > R.x;
            bool s1 = C1.x > R.x;
            float v0 = (s0 ? R.y : R.z) * (s0 ? C0.y : C0.z);
            float v1 = (s1 ? R.y : R.z) * (s1 ? C1.y : C1.z);
            v0 = av[u].x > 0 ? v0 : 0.f;
            v1 = av[u].y > 0 ? v1 : 0.f;
            *(__half2*)&Psb[row * PSS + c0] = __floats2half2_rn(v0, v1);
        }

        // ---- batch HI: 16 adj loads, MMA(t-1) kk 4..7 under them ----
#pragma unroll
        for (int u = 0; u < 16; u++)
            av[u] = __ldg((const int2*)(adjp + (size_t)(16 + u) * N_NODES));

        if (t > 0) mma_half(pab, pvb, lane, c, 4);

#pragma unroll
        for (int u = 0; u < 16; u++) {
            int row = rq * 32 + 16 + u;
            float4 R = rowc[row];
            bool s0 = C0.x > R.x;
            bool s1 = C1.x > R.x;
            float v0 = (s0 ? R.y : R.z) * (s0 ? C0.y : C0.z);
            float v1 = (s1 ? R.y : R.z) * (s1 ? C1.y : C1.z);
            v0 = av[u].x > 0 ? v0 : 0.f;
            v1 = av[u].y > 0 ? v1 : 0.f;
            *(__half2*)&Psb[row * PSS + c0] = __floats2half2_rn(v0, v1);
        }
        __syncthreads();   // single barrier per tile
    }

    // ---- drain: MMA for the last tile ----
    {
        int buf = (JTILES - 1) & 1;
        mma_half(ps_u + buf * PS_BYTES + a_off, vs_u + buf * VS_BYTES, lane, c, 0);
        mma_half(ps_u + buf * PS_BYTES + a_off, vs_u + buf * VS_BYTES, lane, c, 4);
    }

    // ---- store partials (numerator cols 0..63, denom col 64) ----
    float* pp = g_part + ((size_t)blockIdx.y * N_NODES + i0) * NV;
    int r0 = m0 + (lane >> 2);
    int cb = (lane & 3) * 2;
#pragma unroll
    for (int ng = 0; ng < 9; ng++) {
        *(float2*)&pp[(size_t)r0 * NV + ng * 8 + cb]       = make_float2(c[ng][0], c[ng][1]);
        *(float2*)&pp[(size_t)(r0 + 8) * NV + ng * 8 + cb] = make_float2(c[ng][2], c[ng][3]);
    }
}

// ---------------------------------------------------------------------------
// Reduce: sum 16 split-partials, divide by denom (col 64), ELU, store.
// ---------------------------------------------------------------------------
__global__ __launch_bounds__(128) void reduce_kernel(float* __restrict__ out) {
    int tid = threadIdx.x;
    int row = blockIdx.x * 4 + (tid >> 5);
    int cp  = tid & 31;

    size_t base = (size_t)row * NV;
    float denom = 0.f, n0 = 0.f, n1 = 0.f;
#pragma unroll
    for (int s = 0; s < JSPLIT; s++) {
        const float* p = g_part + (size_t)s * N_NODES * NV + base;
        denom += __ldg(&p[64]);
        float2 v = *(const float2*)(p + 2 * cp);
        n0 += v.x;
        n1 += v.y;
    }
    float inv = 1.0f / denom;
    float h0 = n0 * inv, h1 = n1 * inv;
    h0 = h0 > 0.f ? h0 : expm1f(h0);
    h1 = h1 > 0.f ? h1 : expm1f(h1);
    *(float2*)&out[(size_t)row * OUT_F + 2 * cp] = make_float2(h0, h1);
}

// ---------------------------------------------------------------------------
extern "C" void kernel_launch(void* const* d_in, const int* in_sizes, int n_in,
                              void* d_out, int out_size) {
    const float* x   = (const float*)d_in[0];   // [16384, 128] f32
    const int*   adj = (const int*)d_in[1];     // [16384, 16384] i32
    const float* w   = (const float*)d_in[2];   // [128, 64] f32
    const float* aw  = (const float*)d_in[3];   // [128, 1] f32
    float* out = (float*)d_out;                 // [16384, 64] f32

    cudaFuncSetAttribute(gat_main, cudaFuncAttributeMaxDynamicSharedMemorySize,
                         SMEM_TOTAL);

    wh_kernel<<<N_NODES / 32, 256>>>(x, w);
    f_kernel<<<N_NODES / 256, 256>>>(aw);
    gat_main<<<dim3(IBLOCKS, JSPLIT), 256, SMEM_TOTAL>>>(adj);
    reduce_kernel<<<N_NODES / 4, 128>>>(out);
}